// round 7
// baseline (speedup 1.0000x reference)
#include <cuda_runtime.h>
#include <cuda_fp16.h>
#include <cstdint>

// ---------------------------------------------------------------------------
// Problem constants
// ---------------------------------------------------------------------------
constexpr int NROW = 8192;
constexpr int TOT  = 8192;
constexpr int ROWS_TOTAL = 131072;   // 8192*(1+3+5+7)

// ---------------------------------------------------------------------------
// Device scratch
// ---------------------------------------------------------------------------
__device__ __align__(128) __half g_xT[(size_t)ROWS_TOTAL * 512];   // fp16 x, K(u)-major
__device__ __align__(128) __half g_w[4 * 512 * 512];               // fp16 w, [seg][v][u]

// ---------------------------------------------------------------------------
// PTX helpers (compute_103-safe: cp.async / ldmatrix / mma.sync only)
// ---------------------------------------------------------------------------
__device__ __forceinline__ uint32_t smem_u32(const void* p) {
    uint32_t a;
    asm("{ .reg .u64 t; cvta.to.shared.u64 t, %1; cvt.u32.u64 %0, t; }"
        : "=r"(a) : "l"(p));
    return a;
}
__device__ __forceinline__ uint32_t swz(uint32_t off) {        // SW128 pattern
    return off ^ ((off >> 3) & 0x70);
}
__device__ __forceinline__ void cpa16(uint32_t s, const void* g) {
    asm volatile("cp.async.cg.shared.global [%0], [%1], 16;" :: "r"(s), "l"(g));
}
template<int N> __device__ __forceinline__ void cpwait() {
    asm volatile("cp.async.wait_group %0;" :: "n"(N) : "memory");
}
__device__ __forceinline__ void cpcommit() {
    asm volatile("cp.async.commit_group;" ::: "memory");
}
__device__ __forceinline__ void ldmx4(uint32_t* r, uint32_t addr) {
    asm volatile("ldmatrix.sync.aligned.m8n8.x4.shared.b16 {%0,%1,%2,%3}, [%4];"
        : "=r"(r[0]), "=r"(r[1]), "=r"(r[2]), "=r"(r[3]) : "r"(addr));
}
__device__ __forceinline__ void mma16816(float* c, const uint32_t* a,
                                         uint32_t b0, uint32_t b1) {
    asm volatile(
        "mma.sync.aligned.m16n8k16.row.col.f32.f16.f16.f32 "
        "{%0,%1,%2,%3}, {%4,%5,%6,%7}, {%8,%9}, {%0,%1,%2,%3};"
        : "+f"(c[0]), "+f"(c[1]), "+f"(c[2]), "+f"(c[3])
        : "r"(a[0]), "r"(a[1]), "r"(a[2]), "r"(a[3]), "r"(b0), "r"(b1));
}

// ---------------------------------------------------------------------------
// Prep: w -> fp16, transposed to [v][u] K-major (no scale; scale in epilogue)
// ---------------------------------------------------------------------------
__global__ void __launch_bounds__(256)
prep_w(const float* __restrict__ w0, const float* __restrict__ w1,
       const float* __restrict__ w2, const float* __restrict__ w3)
{
    __shared__ float t[32][33];
    const float* w = (blockIdx.z == 0) ? w0 : (blockIdx.z == 1) ? w1
                   : (blockIdx.z == 2) ? w2 : w3;
    const int v0 = blockIdx.x * 32, u0 = blockIdx.y * 32;
    const int tx = threadIdx.x & 31, ty = threadIdx.x >> 5;

    for (int uu = ty; uu < 32; uu += 8)
        t[uu][tx] = w[(size_t)(u0 + uu) * 512 + v0 + tx];
    __syncthreads();

    const size_t segb = (size_t)blockIdx.z * 262144;
    for (int vv = ty; vv < 32; vv += 8)
        g_w[segb + (size_t)(v0 + vv) * 512 + u0 + tx] = __float2half_rn(t[tx][vv]);
}

// ---------------------------------------------------------------------------
// Prep: x -> xT fp16  ([u][i] -> [(n,i)][u] per segment)
// ---------------------------------------------------------------------------
__global__ void __launch_bounds__(256)
prep_x(const float* __restrict__ x)
{
    __shared__ float sx[3584];
    const int n   = blockIdx.x;
    const int tid = threadIdx.x;

    #pragma unroll
    for (int s = 0; s < 4; ++s) {
        const int d   = (s == 0) ? 1 : (s == 1) ? 3 : (s == 2) ? 5 : 7;
        const int off = (s == 0) ? 0 : (s == 1) ? 512 : (s == 2) ? 2048 : 4608;
        const int rb  = (s == 0) ? 0 : (s == 1) ? 8192 : (s == 2) ? 32768 : 73728;
        const int nf  = 512 * d;

        const float4* src = (const float4*)(x + (size_t)n * TOT + off);
        for (int idx = tid; idx < nf / 4; idx += 256)
            ((float4*)sx)[idx] = src[idx];
        __syncthreads();

        for (int e2 = tid; e2 < nf / 2; e2 += 256) {
            const int e = 2 * e2;
            const int u = e & 511;          // e = i*512 + u
            const int i = e >> 9;
            __half2 p;
            p.x = __float2half_rn(sx[u * d + i]);
            p.y = __float2half_rn(sx[(u + 1) * d + i]);
            *(__half2*)&g_xT[((size_t)rb + (size_t)n * d + i) * 512 + u] = p;
        }
        __syncthreads();
    }
}

// ---------------------------------------------------------------------------
// Main GEMM body (mma.sync fp16, 3-stage pipeline, 1 sync/iter):
//   C[m=(n,i)][v] = sum_u X[m][u] * W[v][u];  scaled in fp32 epilogue.
// CTA tile 256(m) x 128(v), warp tile 64x64, BK=64, 1 CTA/SM.
// ---------------------------------------------------------------------------
constexpr int STAGE    = 49152;            // X 32K + W 16K
constexpr int NSTAGE   = 3;
constexpr int SMEM_DYN = NSTAGE * STAGE;   // 144 KB (epilogue needs 132 KB)

template<int SEG, int D, int OFF, int ROWBASE>
__device__ __forceinline__ void gemm_body(float* __restrict__ out, int lb, char* sm)
{
    const int tid  = threadIdx.x;
    const int lane = tid & 31;
    const int wid  = tid >> 5;
    const int vb   = (lb & 3) * 128;       // v-tile base (fast -> L2 X reuse)
    const int mb   = (lb >> 2) * 256;      // m-tile base
    const int wm   = (wid >> 1) * 64;      // warp m offset (4 x 2 warp grid)
    const int wn   = (wid & 1) * 64;       // warp v offset
    const uint32_t smb = smem_u32(sm);

    const __half* Xt = g_xT + (size_t)ROWBASE * 512;
    const __half* W  = g_w  + (size_t)SEG * 262144;

    // gmem load addressing (per thread)
    const int lr = tid >> 3, lg = tid & 7;           // 32 rows x 8 chunks
    const uint32_t lso = swz((uint32_t)(lr * 128 + lg * 16));

    auto load_chunk = [&](int kc, int buf) {
        const uint32_t base = smb + buf * STAGE;
        const int kcol = kc * 64 + lg * 8;
        #pragma unroll
        for (int j = 0; j < 8; ++j)                  // X: 256 rows
            cpa16(base + lso + j * 4096,
                  Xt + (size_t)(mb + lr + j * 32) * 512 + kcol);
        #pragma unroll
        for (int j = 0; j < 4; ++j)                  // W: 128 rows
            cpa16(base + 32768 + lso + j * 4096,
                  W + (size_t)(vb + lr + j * 32) * 512 + kcol);
        cpcommit();
    };

    float acc[4][8][4] = {};

    // ldmatrix lane addressing (swizzle-invariant row steps hoisted: +2048B)
    const int a_m  = (lane & 7) + ((lane >> 3) & 1) * 8;
    const int a_kb = ((lane >> 4) & 1) * 16;
    const int b_n  = (lane & 7) + ((lane >> 4) & 1) * 8;
    const int b_kb = ((lane >> 3) & 1) * 16;
    const uint32_t aBase = (uint32_t)((wm + a_m) * 128 + a_kb);
    const uint32_t bBase = (uint32_t)((wn + b_n) * 128 + b_kb);

    auto compute = [&](int buf) {
        const uint32_t baseX = smb + buf * STAGE;
        const uint32_t baseW = baseX + 32768;
        #pragma unroll
        for (int ks = 0; ks < 4; ++ks) {
            uint32_t a[4][4], b[4][4];
            const uint32_t aA = baseX + swz(aBase + ks * 32);
            const uint32_t bA = baseW + swz(bBase + ks * 32);
            #pragma unroll
            for (int mk = 0; mk < 4; ++mk) ldmx4(a[mk], aA + mk * 2048);
            #pragma unroll
            for (int nh = 0; nh < 4; ++nh) ldmx4(b[nh], bA + nh * 2048);
            #pragma unroll
            for (int mk = 0; mk < 4; ++mk)
                #pragma unroll
                for (int nb = 0; nb < 8; ++nb)
                    mma16816(acc[mk][nb], a[mk],
                             b[nb >> 1][(nb & 1) * 2], b[nb >> 1][(nb & 1) * 2 + 1]);
        }
    };

    load_chunk(0, 0);
    load_chunk(1, 1);
    #pragma unroll 1
    for (int k = 0; k < 8; ++k) {
        if (k < 7) cpwait<1>(); else cpwait<0>();
        __syncthreads();
        compute(k % 3);
        if (k < 6) load_chunk(k + 2, (k + 2) % 3);
    }

    // ---- epilogue: acc -> smem [m][v] (stride 132) -> contiguous stores ----
    __syncthreads();                       // all compute done before smem reuse
    const float SC = 0.044194173824159216f;    // 1/sqrt(512)
    float* so = (float*)sm;
    #pragma unroll
    for (int mk = 0; mk < 4; ++mk)
        #pragma unroll
        for (int nb = 0; nb < 8; ++nb) {
            const int row = wm + mk * 16 + (lane >> 2);
            const int col = wn + nb * 8 + (lane & 3) * 2;
            float2 v0 = make_float2(acc[mk][nb][0] * SC, acc[mk][nb][1] * SC);
            float2 v1 = make_float2(acc[mk][nb][2] * SC, acc[mk][nb][3] * SC);
            *(float2*)&so[row * 132 + col]       = v0;
            *(float2*)&so[(row + 8) * 132 + col] = v1;
        }
    __syncthreads();

    const int n0 = mb / D;
    const int n1 = (mb + 255) / D;
    constexpr int SPAN = 128 * D;              // contiguous out floats per n
    const int total = (n1 - n0 + 1) * SPAN;
    for (int t = tid; t < total; t += 256) {
        const int ni = t / SPAN;
        const int jj = t - ni * SPAN;
        const int n  = n0 + ni;
        const int vl = jj / D;
        const int i  = jj - vl * D;
        const int m  = n * D + i;
        if (m >= mb && m < mb + 256)
            out[(size_t)n * TOT + OFF + (size_t)vb * D + jj] =
                so[(m - mb) * 132 + vl];
    }
}

// Merged kernel: all 4 segments in one launch (single tail wave).
// seg CTA counts: 128 / 384 / 640 / 896  (total 2048)
__global__ void __launch_bounds__(256, 1)
gemm_all(float* __restrict__ out)
{
    extern __shared__ __align__(1024) char sm[];
    const int bid = blockIdx.x;
    if      (bid < 128)  gemm_body<0, 1, 0,    0>    (out, bid,        sm);
    else if (bid < 512)  gemm_body<1, 3, 512,  8192> (out, bid - 128,  sm);
    else if (bid < 1152) gemm_body<2, 5, 2048, 32768>(out, bid - 512,  sm);
    else                 gemm_body<3, 7, 4608, 73728>(out, bid - 1152, sm);
}

// ---------------------------------------------------------------------------
// launch
// ---------------------------------------------------------------------------
extern "C" void kernel_launch(void* const* d_in, const int* in_sizes, int n_in,
                              void* d_out, int out_size)
{
    const float* x  = (const float*)d_in[0];
    const float* w0 = (const float*)d_in[1];
    const float* w1 = (const float*)d_in[2];
    const float* w2 = (const float*)d_in[3];
    const float* w3 = (const float*)d_in[4];
    float* out = (float*)d_out;

    cudaFuncSetAttribute(gemm_all, cudaFuncAttributeMaxDynamicSharedMemorySize, SMEM_DYN);

    prep_w<<<dim3(16, 16, 4), 256>>>(w0, w1, w2, w3);
    prep_x<<<NROW, 256>>>(x);

    gemm_all<<<2048, 256, SMEM_DYN>>>(out);
}

// round 8
// speedup vs baseline: 1.1540x; 1.1540x over previous
#include <cuda_runtime.h>
#include <cuda_fp16.h>
#include <cstdint>

// ---------------------------------------------------------------------------
// Problem constants
// ---------------------------------------------------------------------------
constexpr int NROW = 8192;
constexpr int TOT  = 8192;
constexpr int ROWS_TOTAL = 131072;   // 8192*(1+3+5+7)

// ---------------------------------------------------------------------------
// Device scratch
// ---------------------------------------------------------------------------
__device__ __align__(128) __half g_xT[(size_t)ROWS_TOTAL * 512];   // fp16 x, K(u)-major
__device__ __align__(128) __half g_w[4 * 512 * 512];               // fp16 w, [seg][v][u]

// ---------------------------------------------------------------------------
// PTX helpers (compute_103-safe: cp.async / ldmatrix / mma.sync only)
// ---------------------------------------------------------------------------
__device__ __forceinline__ uint32_t smem_u32(const void* p) {
    uint32_t a;
    asm("{ .reg .u64 t; cvta.to.shared.u64 t, %1; cvt.u32.u64 %0, t; }"
        : "=r"(a) : "l"(p));
    return a;
}
__device__ __forceinline__ uint32_t swz(uint32_t off) {        // SW128 pattern
    return off ^ ((off >> 3) & 0x70);
}
__device__ __forceinline__ void cpa16(uint32_t s, const void* g) {
    asm volatile("cp.async.cg.shared.global [%0], [%1], 16;" :: "r"(s), "l"(g));
}
template<int N> __device__ __forceinline__ void cpwait() {
    asm volatile("cp.async.wait_group %0;" :: "n"(N) : "memory");
}
__device__ __forceinline__ void cpcommit() {
    asm volatile("cp.async.commit_group;" ::: "memory");
}
__device__ __forceinline__ void ldmx4(uint32_t* r, uint32_t addr) {
    asm volatile("ldmatrix.sync.aligned.m8n8.x4.shared.b16 {%0,%1,%2,%3}, [%4];"
        : "=r"(r[0]), "=r"(r[1]), "=r"(r[2]), "=r"(r[3]) : "r"(addr));
}
__device__ __forceinline__ void mma16816(float* c, const uint32_t* a,
                                         uint32_t b0, uint32_t b1) {
    asm volatile(
        "mma.sync.aligned.m16n8k16.row.col.f32.f16.f16.f32 "
        "{%0,%1,%2,%3}, {%4,%5,%6,%7}, {%8,%9}, {%0,%1,%2,%3};"
        : "+f"(c[0]), "+f"(c[1]), "+f"(c[2]), "+f"(c[3])
        : "r"(a[0]), "r"(a[1]), "r"(a[2]), "r"(a[3]), "r"(b0), "r"(b1));
}

// ---------------------------------------------------------------------------
// Prep: w -> fp16, transposed to [v][u] K-major (no scale; scale in epilogue)
// ---------------------------------------------------------------------------
__global__ void __launch_bounds__(256)
prep_w(const float* __restrict__ w0, const float* __restrict__ w1,
       const float* __restrict__ w2, const float* __restrict__ w3)
{
    __shared__ float t[32][33];
    const float* w = (blockIdx.z == 0) ? w0 : (blockIdx.z == 1) ? w1
                   : (blockIdx.z == 2) ? w2 : w3;
    const int v0 = blockIdx.x * 32, u0 = blockIdx.y * 32;
    const int tx = threadIdx.x & 31, ty = threadIdx.x >> 5;

    for (int uu = ty; uu < 32; uu += 8)
        t[uu][tx] = w[(size_t)(u0 + uu) * 512 + v0 + tx];
    __syncthreads();

    const size_t segb = (size_t)blockIdx.z * 262144;
    for (int vv = ty; vv < 32; vv += 8)
        g_w[segb + (size_t)(v0 + vv) * 512 + u0 + tx] = __float2half_rn(t[tx][vv]);
}

// ---------------------------------------------------------------------------
// Prep: x -> xT fp16  ([u][i] -> [(n,i)][u] per segment)
// ---------------------------------------------------------------------------
__global__ void __launch_bounds__(256)
prep_x(const float* __restrict__ x)
{
    __shared__ float sx[3584];
    const int n   = blockIdx.x;
    const int tid = threadIdx.x;

    #pragma unroll
    for (int s = 0; s < 4; ++s) {
        const int d   = (s == 0) ? 1 : (s == 1) ? 3 : (s == 2) ? 5 : 7;
        const int off = (s == 0) ? 0 : (s == 1) ? 512 : (s == 2) ? 2048 : 4608;
        const int rb  = (s == 0) ? 0 : (s == 1) ? 8192 : (s == 2) ? 32768 : 73728;
        const int nf  = 512 * d;

        const float4* src = (const float4*)(x + (size_t)n * TOT + off);
        for (int idx = tid; idx < nf / 4; idx += 256)
            ((float4*)sx)[idx] = src[idx];
        __syncthreads();

        for (int e2 = tid; e2 < nf / 2; e2 += 256) {
            const int e = 2 * e2;
            const int u = e & 511;          // e = i*512 + u
            const int i = e >> 9;
            __half2 p;
            p.x = __float2half_rn(sx[u * d + i]);
            p.y = __float2half_rn(sx[(u + 1) * d + i]);
            *(__half2*)&g_xT[((size_t)rb + (size_t)n * d + i) * 512 + u] = p;
        }
        __syncthreads();
    }
}

// ---------------------------------------------------------------------------
// Main GEMM body (mma.sync fp16, 3-stage pipeline, 1 sync/iter):
//   C[m=(n,i)][v] = sum_u X[m][u] * W[v][u];  scaled in fp32 epilogue.
// CTA tile 128x128, warp tile 64x32, BK=64, 2 CTAs/SM (16 warps/SM).
// ---------------------------------------------------------------------------
constexpr int STAGE    = 32768;            // X 16K + W 16K
constexpr int NSTAGE   = 3;
constexpr int SMEM_DYN = NSTAGE * STAGE;   // 96 KB (epilogue needs 67.6 KB)

template<int SEG, int D, int OFF, int ROWBASE>
__device__ __forceinline__ void gemm_body(float* __restrict__ out, int lb, char* sm)
{
    const int tid  = threadIdx.x;
    const int lane = tid & 31;
    const int wid  = tid >> 5;
    const int vb   = (lb & 3) * 128;       // v-tile base (fast -> L2 X reuse)
    const int mb   = (lb >> 2) * 128;      // m-tile base
    const int wm   = (wid & 1) * 64;       // warp M offset (2x4 warp grid)
    const int wn   = (wid >> 1) * 32;      // warp N offset
    const uint32_t smb = smem_u32(sm);

    const __half* Xt = g_xT + (size_t)ROWBASE * 512;
    const __half* W  = g_w  + (size_t)SEG * 262144;

    // gmem load addressing (per thread)
    const int lr = tid >> 3, lg = tid & 7;
    const uint32_t lso = swz((uint32_t)(lr * 128 + lg * 16));

    auto load_chunk = [&](int kc, int buf) {
        const uint32_t base = smb + buf * STAGE;
        const int kcol = kc * 64 + lg * 8;
        #pragma unroll
        for (int j = 0; j < 4; ++j) {
            const int r = lr + j * 32;
            cpa16(base + lso + j * 4096,         Xt + (size_t)(mb + r) * 512 + kcol);
            cpa16(base + 16384 + lso + j * 4096, W  + (size_t)(vb + r) * 512 + kcol);
        }
        cpcommit();
    };

    float acc[4][4][4] = {};

    // ldmatrix lane addressing; swizzled ks-offsets hoisted out of the k-loop
    // (buffer base is a +32KB multiple: above swizzle bits -> plain add).
    const int a_m  = (lane & 7) + ((lane >> 3) & 1) * 8;
    const int a_kb = ((lane >> 4) & 1) * 16;
    const int b_n  = (lane & 7) + ((lane >> 4) & 1) * 8;
    const int b_kb = ((lane >> 3) & 1) * 16;
    uint32_t aOff[4], bOff[4];
    #pragma unroll
    for (int ks = 0; ks < 4; ++ks) {
        aOff[ks] = swz((uint32_t)((wm + a_m) * 128 + a_kb + ks * 32));
        bOff[ks] = 16384u + swz((uint32_t)((wn + b_n) * 128 + b_kb + ks * 32));
    }

    auto compute = [&](int buf) {
        const uint32_t base = smb + buf * STAGE;
        #pragma unroll
        for (int ks = 0; ks < 4; ++ks) {
            uint32_t a[4][4], b[2][4];
            const uint32_t aA = base + aOff[ks];
            const uint32_t bA = base + bOff[ks];
            #pragma unroll
            for (int mk = 0; mk < 4; ++mk) ldmx4(a[mk], aA + mk * 2048);
            #pragma unroll
            for (int nh = 0; nh < 2; ++nh) ldmx4(b[nh], bA + nh * 2048);
            #pragma unroll
            for (int mk = 0; mk < 4; ++mk)
                #pragma unroll
                for (int nb = 0; nb < 4; ++nb)
                    mma16816(acc[mk][nb], a[mk],
                             b[nb >> 1][(nb & 1) * 2], b[nb >> 1][(nb & 1) * 2 + 1]);
        }
    };

    load_chunk(0, 0);
    load_chunk(1, 1);
    #pragma unroll 1
    for (int k = 0; k < 8; ++k) {
        if (k < 7) cpwait<1>(); else cpwait<0>();
        __syncthreads();
        // issue next loads FIRST: buffer (k+2)%3 was consumed in iter k-1,
        // which completed before this barrier -> safe; front-runs DRAM latency.
        if (k < 6) load_chunk(k + 2, (k + 2) % 3);
        compute(k % 3);
    }

    const float SC = 0.044194173824159216f;    // 1/sqrt(512)

    if (D == 1) {
        // direct epilogue: col = v is contiguous in out; 32B stores per 4 lanes
        #pragma unroll
        for (int mk = 0; mk < 4; ++mk)
            #pragma unroll
            for (int nb = 0; nb < 4; ++nb) {
                const int row = wm + mk * 16 + (lane >> 2);
                const int col = wn + nb * 8 + (lane & 3) * 2;
                float2 v0 = make_float2(acc[mk][nb][0] * SC, acc[mk][nb][1] * SC);
                float2 v1 = make_float2(acc[mk][nb][2] * SC, acc[mk][nb][3] * SC);
                *(float2*)&out[(size_t)(mb + row) * TOT + OFF + vb + col]     = v0;
                *(float2*)&out[(size_t)(mb + row + 8) * TOT + OFF + vb + col] = v1;
            }
        return;
    }

    // ---- epilogue: acc -> smem [m][v] (stride 132) -> contiguous stores ----
    __syncthreads();                       // all LDSM reads done before smem reuse
    float* so = (float*)sm;
    #pragma unroll
    for (int mk = 0; mk < 4; ++mk)
        #pragma unroll
        for (int nb = 0; nb < 4; ++nb) {
            const int row = wm + mk * 16 + (lane >> 2);
            const int col = wn + nb * 8 + (lane & 3) * 2;
            float2 v0 = make_float2(acc[mk][nb][0] * SC, acc[mk][nb][1] * SC);
            float2 v1 = make_float2(acc[mk][nb][2] * SC, acc[mk][nb][3] * SC);
            *(float2*)&so[row * 132 + col]       = v0;
            *(float2*)&so[(row + 8) * 132 + col] = v1;
        }
    __syncthreads();

    const int n0 = mb / D;
    const int n1 = (mb + 127) / D;
    constexpr int SPAN = 128 * D;              // contiguous out floats per n
    const int total = (n1 - n0 + 1) * SPAN;
    for (int t = tid; t < total; t += 256) {
        const int ni = t / SPAN;
        const int jj = t - ni * SPAN;
        const int n  = n0 + ni;
        const int vl = jj / D;
        const int i  = jj - vl * D;
        const int m  = n * D + i;
        if (m >= mb && m < mb + 128)
            out[(size_t)n * TOT + OFF + (size_t)vb * D + jj] =
                so[(m - mb) * 132 + vl];
    }
}

// Merged kernel: all 4 segments in one launch (single tail wave).
// seg CTA counts: 256 / 768 / 1280 / 1792  (total 4096)
__global__ void __launch_bounds__(256, 2)
gemm_all(float* __restrict__ out)
{
    extern __shared__ __align__(1024) char sm[];
    const int bid = blockIdx.x;
    if      (bid < 256)  gemm_body<0, 1, 0,    0>    (out, bid,        sm);
    else if (bid < 1024) gemm_body<1, 3, 512,  8192> (out, bid - 256,  sm);
    else if (bid < 2304) gemm_body<2, 5, 2048, 32768>(out, bid - 1024, sm);
    else                 gemm_body<3, 7, 4608, 73728>(out, bid - 2304, sm);
}

// ---------------------------------------------------------------------------
// launch
// ---------------------------------------------------------------------------
extern "C" void kernel_launch(void* const* d_in, const int* in_sizes, int n_in,
                              void* d_out, int out_size)
{
    const float* x  = (const float*)d_in[0];
    const float* w0 = (const float*)d_in[1];
    const float* w1 = (const float*)d_in[2];
    const float* w2 = (const float*)d_in[3];
    const float* w3 = (const float*)d_in[4];
    float* out = (float*)d_out;

    cudaFuncSetAttribute(gemm_all, cudaFuncAttributeMaxDynamicSharedMemorySize, SMEM_DYN);

    prep_w<<<dim3(16, 16, 4), 256>>>(w0, w1, w2, w3);
    prep_x<<<NROW, 256>>>(x);

    gemm_all<<<4096, 256, SMEM_DYN>>>(out);
}

// round 9
// speedup vs baseline: 1.2593x; 1.0912x over previous
#include <cuda_runtime.h>
#include <cuda_fp16.h>
#include <cstdint>

// ---------------------------------------------------------------------------
// Problem constants
// ---------------------------------------------------------------------------
constexpr int NROW = 8192;
constexpr int TOT  = 8192;
constexpr int ROWS_TOTAL = 131072;   // 8192*(1+3+5+7)

// ---------------------------------------------------------------------------
// Device scratch
// ---------------------------------------------------------------------------
__device__ __align__(128) __half g_xT[(size_t)ROWS_TOTAL * 512];   // fp16 x, K(u)-major
__device__ __align__(128) __half g_w[4 * 512 * 512];               // fp16 w, [seg][v][u]

// ---------------------------------------------------------------------------
// PTX helpers (compute_103-safe: cp.async / ldmatrix / mma.sync only)
// ---------------------------------------------------------------------------
__device__ __forceinline__ uint32_t smem_u32(const void* p) {
    uint32_t a;
    asm("{ .reg .u64 t; cvta.to.shared.u64 t, %1; cvt.u32.u64 %0, t; }"
        : "=r"(a) : "l"(p));
    return a;
}
__device__ __forceinline__ uint32_t swz(uint32_t off) {        // SW128 pattern
    return off ^ ((off >> 3) & 0x70);
}
__device__ __forceinline__ void cpa16(uint32_t s, const void* g) {
    asm volatile("cp.async.cg.shared.global [%0], [%1], 16;" :: "r"(s), "l"(g));
}
template<int N> __device__ __forceinline__ void cpwait() {
    asm volatile("cp.async.wait_group %0;" :: "n"(N) : "memory");
}
__device__ __forceinline__ void cpcommit() {
    asm volatile("cp.async.commit_group;" ::: "memory");
}
__device__ __forceinline__ void ldmx4(uint32_t* r, uint32_t addr) {
    asm volatile("ldmatrix.sync.aligned.m8n8.x4.shared.b16 {%0,%1,%2,%3}, [%4];"
        : "=r"(r[0]), "=r"(r[1]), "=r"(r[2]), "=r"(r[3]) : "r"(addr));
}
__device__ __forceinline__ void mma16816(float* c, const uint32_t* a,
                                         uint32_t b0, uint32_t b1) {
    asm volatile(
        "mma.sync.aligned.m16n8k16.row.col.f32.f16.f16.f32 "
        "{%0,%1,%2,%3}, {%4,%5,%6,%7}, {%8,%9}, {%0,%1,%2,%3};"
        : "+f"(c[0]), "+f"(c[1]), "+f"(c[2]), "+f"(c[3])
        : "r"(a[0]), "r"(a[1]), "r"(a[2]), "r"(a[3]), "r"(b0), "r"(b1));
}

// ---------------------------------------------------------------------------
// Merged prep: blocks [0,8192) transpose/convert x; blocks [8192,9216) do w.
// ---------------------------------------------------------------------------
__global__ void __launch_bounds__(256)
prep_all(const float* __restrict__ x,
         const float* __restrict__ w0, const float* __restrict__ w1,
         const float* __restrict__ w2, const float* __restrict__ w3)
{
    __shared__ float sx[3584];
    const int tid = threadIdx.x;

    if (blockIdx.x >= 8192) {
        // ---- w prep: 1024 blocks, 32x32 transpose tiles ----
        const int wb = blockIdx.x - 8192;
        const int bz = wb >> 8, bx = wb & 15, by = (wb >> 4) & 15;
        const float* w = (bz == 0) ? w0 : (bz == 1) ? w1 : (bz == 2) ? w2 : w3;
        const int v0 = bx * 32, u0 = by * 32;
        const int tx = tid & 31, ty = tid >> 5;
        float (*t)[33] = (float(*)[33])sx;

        for (int uu = ty; uu < 32; uu += 8)
            t[uu][tx] = w[(size_t)(u0 + uu) * 512 + v0 + tx];
        __syncthreads();

        const size_t segb = (size_t)bz * 262144;
        for (int vv = ty; vv < 32; vv += 8)
            g_w[segb + (size_t)(v0 + vv) * 512 + u0 + tx] = __float2half_rn(t[tx][vv]);
        return;
    }

    // ---- x prep: per-row transpose [u][i] -> [(n,i)][u], fp16 ----
    const int n = blockIdx.x;
    #pragma unroll
    for (int s = 0; s < 4; ++s) {
        const int d   = (s == 0) ? 1 : (s == 1) ? 3 : (s == 2) ? 5 : 7;
        const int off = (s == 0) ? 0 : (s == 1) ? 512 : (s == 2) ? 2048 : 4608;
        const int rb  = (s == 0) ? 0 : (s == 1) ? 8192 : (s == 2) ? 32768 : 73728;
        const int nf  = 512 * d;

        const float4* src = (const float4*)(x + (size_t)n * TOT + off);
        for (int idx = tid; idx < nf / 4; idx += 256)
            ((float4*)sx)[idx] = src[idx];
        __syncthreads();

        for (int e2 = tid; e2 < nf / 2; e2 += 256) {
            const int e = 2 * e2;
            const int u = e & 511;          // e = i*512 + u
            const int i = e >> 9;
            __half2 p;
            p.x = __float2half_rn(sx[u * d + i]);
            p.y = __float2half_rn(sx[(u + 1) * d + i]);
            *(__half2*)&g_xT[((size_t)rb + (size_t)n * d + i) * 512 + u] = p;
        }
        __syncthreads();
    }
}

// ---------------------------------------------------------------------------
// Main GEMM body (mma.sync fp16, 3-stage pipeline, 1 sync/iter):
//   C[m=(n,i)][v] = sum_u X[m][u] * W[v][u];  scaled in fp32 epilogue.
// CTA tile 128x128, warp tile 64x32, BK=64, 2 CTAs/SM (16 warps/SM).
// ---------------------------------------------------------------------------
constexpr int STAGE    = 32768;            // X 16K + W 16K
constexpr int NSTAGE   = 3;
constexpr int SMEM_DYN = NSTAGE * STAGE;   // 96 KB (epilogue needs 67.6 KB)

template<int SEG, int D, int OFF, int ROWBASE>
__device__ __forceinline__ void gemm_body(float* __restrict__ out, int lb, char* sm)
{
    const int tid  = threadIdx.x;
    const int lane = tid & 31;
    const int wid  = tid >> 5;
    const int vb   = (lb & 3) * 128;       // v-tile base (fast -> L2 X reuse)
    const int mb   = (lb >> 2) * 128;      // m-tile base
    const int wm   = (wid & 1) * 64;       // warp M offset (2x4 warp grid)
    const int wn   = (wid >> 1) * 32;      // warp N offset
    const uint32_t smb = smem_u32(sm);

    const __half* Xt = g_xT + (size_t)ROWBASE * 512;
    const __half* W  = g_w  + (size_t)SEG * 262144;

    // gmem load addressing (per thread)
    const int lr = tid >> 3, lg = tid & 7;
    const uint32_t lso = swz((uint32_t)(lr * 128 + lg * 16));

    auto load_chunk = [&](int kc, int buf) {
        const uint32_t base = smb + buf * STAGE;
        const int kcol = kc * 64 + lg * 8;
        #pragma unroll
        for (int j = 0; j < 4; ++j) {
            const int r = lr + j * 32;
            cpa16(base + lso + j * 4096,         Xt + (size_t)(mb + r) * 512 + kcol);
            cpa16(base + 16384 + lso + j * 4096, W  + (size_t)(vb + r) * 512 + kcol);
        }
        cpcommit();
    };

    float acc[4][4][4] = {};

    // ldmatrix lane addressing (swizzle-invariant row steps hoisted: +2048B)
    const int a_m  = (lane & 7) + ((lane >> 3) & 1) * 8;
    const int a_kb = ((lane >> 4) & 1) * 16;
    const int b_n  = (lane & 7) + ((lane >> 4) & 1) * 8;
    const int b_kb = ((lane >> 3) & 1) * 16;
    const uint32_t aBase = (uint32_t)((wm + a_m) * 128 + a_kb);
    const uint32_t bBase = (uint32_t)((wn + b_n) * 128 + b_kb);

    auto compute = [&](int buf) {
        const uint32_t baseX = smb + buf * STAGE;
        const uint32_t baseW = baseX + 16384;
        #pragma unroll
        for (int ks = 0; ks < 4; ++ks) {
            uint32_t a[4][4], b[2][4];
            const uint32_t aA = baseX + swz(aBase + ks * 32);
            const uint32_t bA = baseW + swz(bBase + ks * 32);
            #pragma unroll
            for (int mk = 0; mk < 4; ++mk) ldmx4(a[mk], aA + mk * 2048);
            #pragma unroll
            for (int nh = 0; nh < 2; ++nh) ldmx4(b[nh], bA + nh * 2048);
            #pragma unroll
            for (int mk = 0; mk < 4; ++mk)
                #pragma unroll
                for (int nb = 0; nb < 4; ++nb)
                    mma16816(acc[mk][nb], a[mk],
                             b[nb >> 1][(nb & 1) * 2], b[nb >> 1][(nb & 1) * 2 + 1]);
        }
    };

    load_chunk(0, 0);
    load_chunk(1, 1);
    #pragma unroll 1
    for (int k = 0; k < 8; ++k) {
        if (k < 7) cpwait<1>(); else cpwait<0>();
        __syncthreads();
        compute(k % 3);
        if (k < 6) load_chunk(k + 2, (k + 2) % 3);
    }

    // ---- epilogue: acc -> smem [m][v] (stride 132) -> contiguous stores ----
    __syncthreads();                       // all compute done before smem reuse
    const float SC = 0.044194173824159216f;    // 1/sqrt(512)
    float* so = (float*)sm;
    #pragma unroll
    for (int mk = 0; mk < 4; ++mk)
        #pragma unroll
        for (int nb = 0; nb < 4; ++nb) {
            const int row = wm + mk * 16 + (lane >> 2);
            const int col = wn + nb * 8 + (lane & 3) * 2;
            float2 v0 = make_float2(acc[mk][nb][0] * SC, acc[mk][nb][1] * SC);
            float2 v1 = make_float2(acc[mk][nb][2] * SC, acc[mk][nb][3] * SC);
            *(float2*)&so[row * 132 + col]       = v0;
            *(float2*)&so[(row + 8) * 132 + col] = v1;
        }
    __syncthreads();

    constexpr int SPAN = 128 * D;              // contiguous out floats per n
    const int n0 = mb / D;

    if (D == 1) {
        // SPAN=128 (power of 2): shifts, already cheap
        const int total = 128 * 128;
        for (int t = tid; t < total; t += 256) {
            const int ni = t >> 7;
            const int vl = t & 127;
            out[(size_t)(n0 + ni) * TOT + OFF + vb + vl] = so[ni * 132 + vl];
        }
        return;
    }

    // division-free epilogue for D in {3,5,7}
    const int base = n0 * D - mb;              // in (-D, 0]
    const int n1 = (mb + 127) / D;
    const int total = (n1 - n0 + 1) * SPAN;
    constexpr int QD = 256 / D, RD = 256 % D;

    int ni = 0;                                // tid < 256 <= SPAN for D>=3
    int jj = tid;
    int vl = jj / D;                           // once, const-div
    int ii = jj - vl * D;

    for (int t = tid; t < total; t += 256) {
        const int mm = ni * D + ii + base;     // m - mb
        if (mm >= 0 && mm < 128)
            out[(size_t)(n0 + ni) * TOT + OFF + (size_t)vb * D + jj] =
                so[mm * 132 + vl];
        // advance linear index by 256 (256 < SPAN: at most one row wrap)
        jj += 256; vl += QD; ii += RD;
        if (ii >= D)    { ii -= D;    vl += 1; }
        if (jj >= SPAN) { jj -= SPAN; vl -= 128; ni += 1; }
    }
}

// Merged kernel: all 4 segments in one launch (single tail wave).
// seg CTA counts: 256 / 768 / 1280 / 1792  (total 4096)
__global__ void __launch_bounds__(256, 2)
gemm_all(float* __restrict__ out)
{
    extern __shared__ __align__(1024) char sm[];
    const int bid = blockIdx.x;
    if      (bid < 256)  gemm_body<0, 1, 0,    0>    (out, bid,        sm);
    else if (bid < 1024) gemm_body<1, 3, 512,  8192> (out, bid - 256,  sm);
    else if (bid < 2304) gemm_body<2, 5, 2048, 32768>(out, bid - 1024, sm);
    else                 gemm_body<3, 7, 4608, 73728>(out, bid - 2304, sm);
}

// ---------------------------------------------------------------------------
// launch
// ---------------------------------------------------------------------------
extern "C" void kernel_launch(void* const* d_in, const int* in_sizes, int n_in,
                              void* d_out, int out_size)
{
    const float* x  = (const float*)d_in[0];
    const float* w0 = (const float*)d_in[1];
    const float* w1 = (const float*)d_in[2];
    const float* w2 = (const float*)d_in[3];
    const float* w3 = (const float*)d_in[4];
    float* out = (float*)d_out;

    cudaFuncSetAttribute(gemm_all, cudaFuncAttributeMaxDynamicSharedMemorySize, SMEM_DYN);

    prep_all<<<9216, 256>>>(x, w0, w1, w2, w3);
    gemm_all<<<4096, 256, SMEM_DYN>>>(out);
}

// round 11
// speedup vs baseline: 1.3368x; 1.0616x over previous
#include <cuda_runtime.h>
#include <cuda_fp16.h>
#include <cuda.h>
#include <cstdint>

// ---------------------------------------------------------------------------
// Problem constants
// ---------------------------------------------------------------------------
constexpr int NROW = 8192;
constexpr int TOT  = 8192;
constexpr int ROWS_TOTAL = 131072;   // 8192*(1+3+5+7)

// ---------------------------------------------------------------------------
// Device scratch
// ---------------------------------------------------------------------------
__device__ __align__(128) __half g_xT[(size_t)ROWS_TOTAL * 512];   // fp16 x, K(u)-major
__device__ __align__(128) __half g_w[4 * 512 * 512];               // fp16 w, [seg][v][u]

// ---------------------------------------------------------------------------
// PTX helpers (compute_103-safe: TMA tile / mbarrier / ldmatrix / mma.sync)
// ---------------------------------------------------------------------------
__device__ __forceinline__ uint32_t smem_u32(const void* p) {
    uint32_t a;
    asm("{ .reg .u64 t; cvta.to.shared.u64 t, %1; cvt.u32.u64 %0, t; }"
        : "=r"(a) : "l"(p));
    return a;
}
__device__ __forceinline__ uint32_t swz(uint32_t off) {        // SW128 pattern
    return off ^ ((off >> 3) & 0x70);
}
__device__ __forceinline__ void ldmx4(uint32_t* r, uint32_t addr) {
    asm volatile("ldmatrix.sync.aligned.m8n8.x4.shared.b16 {%0,%1,%2,%3}, [%4];"
        : "=r"(r[0]), "=r"(r[1]), "=r"(r[2]), "=r"(r[3]) : "r"(addr));
}
__device__ __forceinline__ void mma16816(float* c, const uint32_t* a,
                                         uint32_t b0, uint32_t b1) {
    asm volatile(
        "mma.sync.aligned.m16n8k16.row.col.f32.f16.f16.f32 "
        "{%0,%1,%2,%3}, {%4,%5,%6,%7}, {%8,%9}, {%0,%1,%2,%3};"
        : "+f"(c[0]), "+f"(c[1]), "+f"(c[2]), "+f"(c[3])
        : "r"(a[0]), "r"(a[1]), "r"(a[2]), "r"(a[3]), "r"(b0), "r"(b1));
}
__device__ __forceinline__ void mbar_init(uint32_t mbar, uint32_t cnt) {
    asm volatile("mbarrier.init.shared.b64 [%0], %1;" :: "r"(mbar), "r"(cnt) : "memory");
}
__device__ __forceinline__ void fence_proxy_async_cta() {
    asm volatile("fence.proxy.async.shared::cta;" ::: "memory");
}
__device__ __forceinline__ void mbar_expect_tx(uint32_t mbar, uint32_t bytes) {
    asm volatile("mbarrier.arrive.expect_tx.shared.b64 _, [%0], %1;"
                 :: "r"(mbar), "r"(bytes) : "memory");
}
__device__ __forceinline__ void mbar_arrive(uint32_t mbar) {
    asm volatile("mbarrier.arrive.shared.b64 _, [%0];" :: "r"(mbar) : "memory");
}
__device__ __forceinline__ void mbar_wait(uint32_t mbar, uint32_t parity) {
    asm volatile(
        "{\n\t.reg .pred P;\n"
        "W%=:\n\t"
        "mbarrier.try_wait.parity.acquire.cta.shared::cta.b64 P, [%0], %1, 0x989680;\n\t"
        "@!P bra W%=;\n\t}"
        :: "r"(mbar), "r"(parity) : "memory");
}
__device__ __forceinline__ void tma2d(uint32_t smem, const void* map,
                                      int c0, int c1, uint32_t mbar) {
    asm volatile(
        "cp.async.bulk.tensor.2d.shared::cta.global.tile.mbarrier::complete_tx::bytes "
        "[%0], [%1, {%2, %3}], [%4];"
        :: "r"(smem), "l"(map), "r"(c0), "r"(c1), "r"(mbar) : "memory");
}

// ---------------------------------------------------------------------------
// Merged prep: blocks [0,8192) transpose/convert x; blocks [8192,9216) do w.
// ---------------------------------------------------------------------------
__global__ void __launch_bounds__(256)
prep_all(const float* __restrict__ x,
         const float* __restrict__ w0, const float* __restrict__ w1,
         const float* __restrict__ w2, const float* __restrict__ w3)
{
    __shared__ float sx[3584];
    const int tid = threadIdx.x;

    if (blockIdx.x >= 8192) {
        // ---- w prep: 1024 blocks, 32x32 transpose tiles ----
        const int wb = blockIdx.x - 8192;
        const int bz = wb >> 8, bx = wb & 15, by = (wb >> 4) & 15;
        const float* w = (bz == 0) ? w0 : (bz == 1) ? w1 : (bz == 2) ? w2 : w3;
        const int v0 = bx * 32, u0 = by * 32;
        const int tx = tid & 31, ty = tid >> 5;
        float (*t)[33] = (float(*)[33])sx;

        for (int uu = ty; uu < 32; uu += 8)
            t[uu][tx] = w[(size_t)(u0 + uu) * 512 + v0 + tx];
        __syncthreads();

        const size_t segb = (size_t)bz * 262144;
        for (int vv = ty; vv < 32; vv += 8)
            g_w[segb + (size_t)(v0 + vv) * 512 + u0 + tx] = __float2half_rn(t[tx][vv]);
        return;
    }

    // ---- x prep: per-row transpose [u][i] -> [(n,i)][u], fp16 ----
    const int n = blockIdx.x;
    #pragma unroll
    for (int s = 0; s < 4; ++s) {
        const int d   = (s == 0) ? 1 : (s == 1) ? 3 : (s == 2) ? 5 : 7;
        const int off = (s == 0) ? 0 : (s == 1) ? 512 : (s == 2) ? 2048 : 4608;
        const int rb  = (s == 0) ? 0 : (s == 1) ? 8192 : (s == 2) ? 32768 : 73728;
        const int nf  = 512 * d;

        const float4* src = (const float4*)(x + (size_t)n * TOT + off);
        for (int idx = tid; idx < nf / 4; idx += 256)
            ((float4*)sx)[idx] = src[idx];
        __syncthreads();

        for (int e2 = tid; e2 < nf / 2; e2 += 256) {
            const int e = 2 * e2;
            const int u = e & 511;          // e = i*512 + u
            const int i = e >> 9;
            __half2 p;
            p.x = __float2half_rn(sx[u * d + i]);
            p.y = __float2half_rn(sx[(u + 1) * d + i]);
            *(__half2*)&g_xT[((size_t)rb + (size_t)n * d + i) * 512 + u] = p;
        }
        __syncthreads();
    }
}

// ---------------------------------------------------------------------------
// Main GEMM body (mma.sync fp16, TMA 3-stage pipeline, no syncthreads in loop)
//   C[m=(n,i)][v] = sum_u X[m][u] * W[v][u];  scaled in fp32 epilogue.
// CTA tile 128x128, warp tile 64x32, BK=64, 2 CTAs/SM (16 warps/SM).
// ---------------------------------------------------------------------------
constexpr int STAGE    = 32768;              // X 16K + W 16K
constexpr int MBAR_OFF = 3 * STAGE;          // 98304
constexpr int SMEM_DYN = MBAR_OFF + 48;      // + 3 full + 3 empty mbars

template<int SEG, int D, int OFF, int ROWBASE>
__device__ __forceinline__ void gemm_body(float* __restrict__ out, int lb, char* sm,
                                          const CUtensorMap* tmX, const CUtensorMap* tmW)
{
    const int tid  = threadIdx.x;
    const int lane = tid & 31;
    const int wid  = tid >> 5;
    const int vb   = (lb & 3) * 128;       // v-tile base (fast -> L2 X reuse)
    const int mb   = (lb >> 2) * 128;      // m-tile base
    const int wm   = (wid & 1) * 64;       // warp M offset (2x4 warp grid)
    const int wn   = (wid >> 1) * 32;      // warp N offset
    const uint32_t smb = smem_u32(sm);
    const uint32_t mbF = smb + MBAR_OFF;       // full[3]
    const uint32_t mbE = smb + MBAR_OFF + 24;  // empty[3]

    if (tid == 0) {
        #pragma unroll
        for (int b = 0; b < 3; ++b) {
            mbar_init(mbF + b * 8, 1);     // completed by expect_tx + TMA tx
            mbar_init(mbE + b * 8, 8);     // one arrive per warp
        }
        fence_proxy_async_cta();           // init visible to async (TMA) proxy
    }
    __syncthreads();

    // producer: chunk j -> buffer j%3.  empty parity: ((j/3)&1)^1 (first pass free)
    auto produce = [&](int j) {
        const int buf = j % 3;
        const uint32_t fm = mbF + buf * 8;
        mbar_wait(mbE + buf * 8, ((j / 3) & 1) ^ 1);
        mbar_expect_tx(fm, 2 * 16384);
        tma2d(smb + buf * STAGE,         tmX, j * 64, ROWBASE + mb,  fm);
        tma2d(smb + buf * STAGE + 16384, tmW, j * 64, SEG * 512 + vb, fm);
    };

    float acc[4][4][4] = {};

    // ldmatrix lane addressing (swizzle computed per-ks: swz does NOT
    // distribute over +ks*32 when the XOR pattern occupies bits 5-6!)
    const int a_m  = (lane & 7) + ((lane >> 3) & 1) * 8;
    const int a_kb = ((lane >> 4) & 1) * 16;
    const int b_n  = (lane & 7) + ((lane >> 4) & 1) * 8;
    const int b_kb = ((lane >> 3) & 1) * 16;
    const uint32_t aBase = (uint32_t)((wm + a_m) * 128 + a_kb);
    const uint32_t bBase = (uint32_t)((wn + b_n) * 128 + b_kb);

    auto compute = [&](int buf) {
        const uint32_t baseX = smb + buf * STAGE;
        const uint32_t baseW = baseX + 16384;
        #pragma unroll
        for (int ks = 0; ks < 4; ++ks) {
            uint32_t a[4][4], b[2][4];
            const uint32_t aA = baseX + swz(aBase + ks * 32);
            const uint32_t bA = baseW + swz(bBase + ks * 32);
            #pragma unroll
            for (int mk = 0; mk < 4; ++mk) ldmx4(a[mk], aA + mk * 2048);
            #pragma unroll
            for (int nh = 0; nh < 2; ++nh) ldmx4(b[nh], bA + nh * 2048);
            #pragma unroll
            for (int mk = 0; mk < 4; ++mk)
                #pragma unroll
                for (int nb = 0; nb < 4; ++nb)
                    mma16816(acc[mk][nb], a[mk],
                             b[nb >> 1][(nb & 1) * 2], b[nb >> 1][(nb & 1) * 2 + 1]);
        }
    };

    if (tid == 0) { produce(0); produce(1); }

    #pragma unroll 1
    for (int k = 0; k < 8; ++k) {
        const int buf = k % 3;
        if (tid == 0 && k < 6) produce(k + 2);
        mbar_wait(mbF + buf * 8, (k / 3) & 1);   // acquire: TMA data -> ldmatrix
        compute(buf);
        if (lane == 0) mbar_arrive(mbE + buf * 8);   // warp's LDSM reads done
    }

    // ---- epilogue: acc -> smem [m][v] (stride 132) -> contiguous stores ----
    __syncthreads();                       // all compute done before smem reuse
    const float SC = 0.044194173824159216f;    // 1/sqrt(512)
    float* so = (float*)sm;
    #pragma unroll
    for (int mk = 0; mk < 4; ++mk)
        #pragma unroll
        for (int nb = 0; nb < 4; ++nb) {
            const int row = wm + mk * 16 + (lane >> 2);
            const int col = wn + nb * 8 + (lane & 3) * 2;
            float2 v0 = make_float2(acc[mk][nb][0] * SC, acc[mk][nb][1] * SC);
            float2 v1 = make_float2(acc[mk][nb][2] * SC, acc[mk][nb][3] * SC);
            *(float2*)&so[row * 132 + col]       = v0;
            *(float2*)&so[(row + 8) * 132 + col] = v1;
        }
    __syncthreads();

    constexpr int SPAN = 128 * D;              // contiguous out floats per n
    const int n0 = mb / D;

    if (D == 1) {
        const int total = 128 * 128;
        for (int t = tid; t < total; t += 256) {
            const int ni = t >> 7;
            const int vl = t & 127;
            out[(size_t)(n0 + ni) * TOT + OFF + vb + vl] = so[ni * 132 + vl];
        }
        return;
    }

    // division-free epilogue for D in {3,5,7}
    const int base = n0 * D - mb;              // in (-D, 0]
    const int n1 = (mb + 127) / D;
    const int total = (n1 - n0 + 1) * SPAN;
    constexpr int QD = 256 / D, RD = 256 % D;

    int ni = 0;                                // tid < 256 <= SPAN for D>=3
    int jj = tid;
    int vl = jj / D;                           // once, const-div
    int ii = jj - vl * D;

    for (int t = tid; t < total; t += 256) {
        const int mm = ni * D + ii + base;     // m - mb
        if (mm >= 0 && mm < 128)
            out[(size_t)(n0 + ni) * TOT + OFF + (size_t)vb * D + jj] =
                so[mm * 132 + vl];
        jj += 256; vl += QD; ii += RD;
        if (ii >= D)    { ii -= D;    vl += 1; }
        if (jj >= SPAN) { jj -= SPAN; vl -= 128; ni += 1; }
    }
}

// Merged kernel: all 4 segments in one launch (single tail wave).
// seg CTA counts: 256 / 768 / 1280 / 1792  (total 4096)
__global__ void __launch_bounds__(256, 2)
gemm_all(float* __restrict__ out,
         const __grid_constant__ CUtensorMap tmX,
         const __grid_constant__ CUtensorMap tmW)
{
    extern __shared__ __align__(1024) char sm[];
    const int bid = blockIdx.x;
    if      (bid < 256)  gemm_body<0, 1, 0,    0>    (out, bid,        sm, &tmX, &tmW);
    else if (bid < 1024) gemm_body<1, 3, 512,  8192> (out, bid - 256,  sm, &tmX, &tmW);
    else if (bid < 2304) gemm_body<2, 5, 2048, 32768>(out, bid - 1024, sm, &tmX, &tmW);
    else                 gemm_body<3, 7, 4608, 73728>(out, bid - 2304, sm, &tmX, &tmW);
}

// ---------------------------------------------------------------------------
// host: tensormap construction (driver entry point; no -lcuda needed)
// ---------------------------------------------------------------------------
typedef CUresult (*EncodeFn)(CUtensorMap*, CUtensorMapDataType, cuuint32_t, void*,
                             const cuuint64_t*, const cuuint64_t*, const cuuint32_t*,
                             const cuuint32_t*, CUtensorMapInterleave, CUtensorMapSwizzle,
                             CUtensorMapL2promotion, CUtensorMapFloatOOBfill);

static EncodeFn get_encode_fn() {
    static EncodeFn fn = nullptr;
    if (!fn) {
        void* p = nullptr;
        cudaDriverEntryPointQueryResult st;
        cudaGetDriverEntryPoint("cuTensorMapEncodeTiled", &p, cudaEnableDefault, &st);
        fn = (EncodeFn)p;
    }
    return fn;
}

extern "C" void kernel_launch(void* const* d_in, const int* in_sizes, int n_in,
                              void* d_out, int out_size)
{
    const float* x  = (const float*)d_in[0];
    const float* w0 = (const float*)d_in[1];
    const float* w1 = (const float*)d_in[2];
    const float* w2 = (const float*)d_in[3];
    const float* w3 = (const float*)d_in[4];
    float* out = (float*)d_out;

    // tensormaps over the fixed __device__ scratch (stable across graph replays)
    CUtensorMap tmX{}, tmW{};
    {
        void *pX = nullptr, *pW = nullptr;
        cudaGetSymbolAddress(&pX, g_xT);
        cudaGetSymbolAddress(&pW, g_w);
        EncodeFn enc = get_encode_fn();
        cuuint64_t dimX[2] = {512, (cuuint64_t)ROWS_TOTAL};
        cuuint64_t dimW[2] = {512, 2048};
        cuuint64_t strB[1] = {1024};                     // row stride bytes
        cuuint32_t box[2]  = {64, 128};
        cuuint32_t es[2]   = {1, 1};
        enc(&tmX, CU_TENSOR_MAP_DATA_TYPE_FLOAT16, 2, pX, dimX, strB, box, es,
            CU_TENSOR_MAP_INTERLEAVE_NONE, CU_TENSOR_MAP_SWIZZLE_128B,
            CU_TENSOR_MAP_L2_PROMOTION_L2_128B, CU_TENSOR_MAP_FLOAT_OOB_FILL_NONE);
        enc(&tmW, CU_TENSOR_MAP_DATA_TYPE_FLOAT16, 2, pW, dimW, strB, box, es,
            CU_TENSOR_MAP_INTERLEAVE_NONE, CU_TENSOR_MAP_SWIZZLE_128B,
            CU_TENSOR_MAP_L2_PROMOTION_L2_128B, CU_TENSOR_MAP_FLOAT_OOB_FILL_NONE);
    }

    cudaFuncSetAttribute(gemm_all, cudaFuncAttributeMaxDynamicSharedMemorySize, SMEM_DYN);

    prep_all<<<9216, 256>>>(x, w0, w1, w2, w3);
    gemm_all<<<4096, 256, SMEM_DYN>>>(out, tmX, tmW);
}